// round 13
// baseline (speedup 1.0000x reference)
#include <cuda_runtime.h>
#include <cstdint>

#define NNODES 50000
#define NEDGES 800000
#define ETOT   850000
#define FIN    128
#define H1     4
#define D1     256   // H1*C1
#define D2     64
#define DAGG   512   // H1*FIN
#define CAP    64    // bucket capacity per node
#define NEG_SLOPE 0.2f
#define SCAT_BLK  3321      // ceil(850000/256)
#define ALPHA1_BLK 6250     // ceil(50000/8)

typedef unsigned long long ull;

// ---------------- scratch (static device globals) ---------------------------
static __device__ float    g_aggx[NNODES * DAGG];   // tf32 bits
static __device__ float    g_agg1[NNODES * D1];     // tf32 bits (post bias+ELU)
static __device__ float    g_xl2 [NNODES * D2];
static __device__ uint32_t g_w1tf[FIN * D1];        // W1 as tf32 bits
static __device__ uint32_t g_w2tf[D1 * D2];         // W2 as tf32 bits
static __device__ float    g_ws1 [FIN * H1];
static __device__ float    g_wd1 [FIN * H1];
static __device__ float    g_as1 [NNODES * H1];
static __device__ float    g_ad1 [NNODES * H1];
static __device__ float    g_as2 [NNODES];
static __device__ float    g_ad2 [NNODES];
static __device__ int      g_cnt [NNODES];
static __device__ int      g_srcs[NNODES * CAP];

__device__ __forceinline__ void edge_nodes(const int* __restrict__ ei,
                                           int e, int& s, int& d) {
    if (e < NEDGES) { s = ei[e]; d = ei[NEDGES + e]; }
    else            { s = e - NEDGES; d = s; }
}

__device__ __forceinline__ uint32_t f2tf(float f) {
    uint32_t u;
    asm("cvt.rna.tf32.f32 %0, %1;" : "=r"(u) : "f"(f));
    return u;
}

__device__ __forceinline__ void mma_tf32(float c[4], const uint32_t a[4],
                                         const uint32_t b[2]) {
    asm volatile(
        "mma.sync.aligned.m16n8k8.row.col.f32.tf32.tf32.f32 "
        "{%0,%1,%2,%3}, {%4,%5,%6,%7}, {%8,%9}, {%0,%1,%2,%3};"
        : "+f"(c[0]), "+f"(c[1]), "+f"(c[2]), "+f"(c[3])
        : "r"(a[0]), "r"(a[1]), "r"(a[2]), "r"(a[3]), "r"(b[0]), "r"(b[1]));
}

__device__ __forceinline__ ull pack2(float lo, float hi) {
    ull r;
    asm("mov.b64 %0, {%1, %2};" : "=l"(r) : "f"(lo), "f"(hi));
    return r;
}
__device__ __forceinline__ void unpack2(ull v, float& lo, float& hi) {
    asm("mov.b64 {%0, %1}, %2;" : "=f"(lo), "=f"(hi) : "l"(v));
}
__device__ __forceinline__ ull ffma2(ull a, ull b, ull c) {
    ull d;
    asm("fma.rn.f32x2 %0, %1, %2, %3;" : "=l"(d) : "l"(a), "l"(b), "l"(c));
    return d;
}

__device__ __forceinline__ uint32_t smem_u32(const void* p) {
    return (uint32_t)__cvta_generic_to_shared(p);
}
__device__ __forceinline__ void cp16(uint32_t dst, const void* src, int nbytes) {
    asm volatile("cp.async.ca.shared.global [%0], [%1], 16, %2;"
                 :: "r"(dst), "l"(src), "r"(nbytes));
}
#define CP_COMMIT() asm volatile("cp.async.commit_group;")
#define CP_WAIT(n)  asm volatile("cp.async.wait_group %0;" :: "n"(n))

// ================= kernel 1: zero cnt + w1prep + W1/W2 tf32 cvt ==============
// blocks 0..97: zero cnt | 98: ws/wd | 99..162: W1 cvt | 163..194: W2 cvt
__global__ __launch_bounds__(512) void init_prep_kernel(
    int* __restrict__ cnt, const float* __restrict__ W1,
    const float* __restrict__ W2,
    const float* __restrict__ a_s, const float* __restrict__ a_d,
    float* __restrict__ ws, float* __restrict__ wd,
    uint32_t* __restrict__ w1tf, uint32_t* __restrict__ w2tf) {
    int b = blockIdx.x;
    if (b < 98) {
        int i = b * 512 + threadIdx.x;
        if (i < NNODES) cnt[i] = 0;
    } else if (b == 98) {
        int t = threadIdx.x;
        int c = t >> 2, h = t & 3;
        float accs = 0.f, accd = 0.f;
        #pragma unroll 8
        for (int j = 0; j < 64; j++) {
            float w = W1[c * D1 + h * 64 + j];
            accs += w * a_s[h * 64 + j];
            accd += w * a_d[h * 64 + j];
        }
        ws[c * 4 + h] = accs;
        wd[c * 4 + h] = accd;
    } else if (b < 163) {
        int i = (b - 99) * 512 + threadIdx.x;       // FIN*D1 = 32768
        w1tf[i] = f2tf(W1[i]);
    } else {
        int i = (b - 163) * 512 + threadIdx.x;      // D1*D2 = 16384
        w2tf[i] = f2tf(W2[i]);
    }
}

// ================= kernel 2: bucket scatter + alpha1 (merged) ================
__global__ __launch_bounds__(256) void scatter_alpha1_kernel(
    const int* __restrict__ ei, int* __restrict__ cnt, int* __restrict__ srcs,
    const float* __restrict__ x, const float* __restrict__ ws,
    const float* __restrict__ wd,
    float* __restrict__ asrc, float* __restrict__ adst) {
    if (blockIdx.x < SCAT_BLK) {
        int e = blockIdx.x * 256 + threadIdx.x;
        if (e >= ETOT) return;
        int s, d; edge_nodes(ei, e, s, d);
        int slot = atomicAdd(&cnt[d], 1);
        if (slot < CAP) srcs[d * CAP + slot] = s;
    } else {
        int w = (blockIdx.x - SCAT_BLK) * 8 + (threadIdx.x >> 5);
        int lane = threadIdx.x & 31;
        if (w >= NNODES) return;
        const float* row = x + (long)w * FIN;
        float ps[4] = {}, pd[4] = {};
        #pragma unroll
        for (int j = 0; j < 4; j++) {
            int c = lane + j * 32;
            float v = row[c];
            float4 a = *(const float4*)(ws + c * 4);
            float4 b = *(const float4*)(wd + c * 4);
            ps[0] += v * a.x; ps[1] += v * a.y; ps[2] += v * a.z; ps[3] += v * a.w;
            pd[0] += v * b.x; pd[1] += v * b.y; pd[2] += v * b.z; pd[3] += v * b.w;
        }
        #pragma unroll
        for (int off = 16; off; off >>= 1) {
            #pragma unroll
            for (int h = 0; h < 4; h++) {
                ps[h] += __shfl_xor_sync(0xFFFFFFFFu, ps[h], off);
                pd[h] += __shfl_xor_sync(0xFFFFFFFFu, pd[h], off);
            }
        }
        if (lane == 0) {
            *(float4*)(asrc + w * 4) = make_float4(ps[0], ps[1], ps[2], ps[3]);
            *(float4*)(adst + w * 4) = make_float4(pd[0], pd[1], pd[2], pd[3]);
        }
    }
}

// ================= kernel 3: gather layer1 (writes tf32 bits) ================
__global__ __launch_bounds__(256) void gather1_kernel(
    const int* __restrict__ cnt, const int* __restrict__ srcs,
    const float* __restrict__ asrc, const float* __restrict__ adst,
    const float* __restrict__ x, float* __restrict__ aggx) {
    __shared__ int sm_s  [8][32];
    __shared__ ull sm_dup[8][32][4];
    int wslot = threadIdx.x >> 5;
    int node = blockIdx.x * 8 + wslot;
    if (node >= NNODES) return;
    int lane = threadIdx.x & 31;
    int deg = min(cnt[node], CAP);
    const int* bucket = srcs + node * CAP;
    float4 ad = *(const float4*)(adst + node * 4);
    ull accl[4], acch[4];
    #pragma unroll
    for (int h = 0; h < 4; h++) { accl[h] = 0ull; acch[h] = 0ull; }
    float exs[4] = {};
    for (int base = 0; base < deg; base += 32) {
        int j = base + lane;
        if (j < deg) {
            int sv = __ldg(bucket + j);
            float4 as = *(const float4*)(asrc + sv * 4);
            float v;
            float4 ex;
            v = as.x + ad.x; v = v > 0.f ? v : v * NEG_SLOPE; ex.x = __expf(v);
            v = as.y + ad.y; v = v > 0.f ? v : v * NEG_SLOPE; ex.y = __expf(v);
            v = as.z + ad.z; v = v > 0.f ? v : v * NEG_SLOPE; ex.z = __expf(v);
            v = as.w + ad.w; v = v > 0.f ? v : v * NEG_SLOPE; ex.w = __expf(v);
            exs[0] += ex.x; exs[1] += ex.y; exs[2] += ex.z; exs[3] += ex.w;
            sm_s[wslot][lane] = sv;
            sm_dup[wslot][lane][0] = pack2(ex.x, ex.x);
            sm_dup[wslot][lane][1] = pack2(ex.y, ex.y);
            sm_dup[wslot][lane][2] = pack2(ex.z, ex.z);
            sm_dup[wslot][lane][3] = pack2(ex.w, ex.w);
        }
        __syncwarp();
        int m = min(32, deg - base);
        for (int t = 0; t < m; t++) {
            int s = sm_s[wslot][t];
            ulonglong2 e01 = *(const ulonglong2*)&sm_dup[wslot][t][0];
            ulonglong2 e23 = *(const ulonglong2*)&sm_dup[wslot][t][2];
            ulonglong2 v = __ldg((const ulonglong2*)(x + (long)s * FIN + lane * 4));
            accl[0] = ffma2(v.x, e01.x, accl[0]);
            acch[0] = ffma2(v.y, e01.x, acch[0]);
            accl[1] = ffma2(v.x, e01.y, accl[1]);
            acch[1] = ffma2(v.y, e01.y, acch[1]);
            accl[2] = ffma2(v.x, e23.x, accl[2]);
            acch[2] = ffma2(v.y, e23.x, acch[2]);
            accl[3] = ffma2(v.x, e23.y, accl[3]);
            acch[3] = ffma2(v.y, e23.y, acch[3]);
        }
        __syncwarp();
    }
    #pragma unroll
    for (int off = 16; off; off >>= 1)
        #pragma unroll
        for (int h = 0; h < 4; h++)
            exs[h] += __shfl_xor_sync(0xFFFFFFFFu, exs[h], off);
    uint32_t* o = (uint32_t*)(aggx + (long)node * DAGG + lane * 4);
    #pragma unroll
    for (int h = 0; h < 4; h++) {
        float inv = 1.f / exs[h];
        float a0, a1, a2, a3;
        unpack2(accl[h], a0, a1);
        unpack2(acch[h], a2, a3);
        *(uint4*)(o + h * FIN) = make_uint4(f2tf(a0 * inv), f2tf(a1 * inv),
                                            f2tf(a2 * inv), f2tf(a3 * inv));
    }
}

// ================= tf32 GEMM core (BM=128, BN=64, BK=32, 8 warps) ============
// dynamic smem: As[2][128][36] then Bs[2][32][72], tf32 bits.
#define AS_PITCH 36
#define BS_PITCH 72
#define AS_SZ (128 * AS_PITCH)
#define BS_SZ (32 * BS_PITCH)
#define GEMM_DYN ((2 * AS_SZ + 2 * BS_SZ) * 4)

__device__ __forceinline__ void mma_block(
    const uint32_t* __restrict__ As, const uint32_t* __restrict__ Bs,
    int lane, int wm, int wn, float acc[2][4][4]) {
    #pragma unroll
    for (int k8 = 0; k8 < 4; k8++) {
        int kb = k8 * 8;
        uint32_t a[2][4];
        #pragma unroll
        for (int mt = 0; mt < 2; mt++) {
            int row = wm * 32 + mt * 16 + (lane >> 2);
            int col = kb + (lane & 3);
            a[mt][0] = As[row * AS_PITCH + col];
            a[mt][1] = As[(row + 8) * AS_PITCH + col];
            a[mt][2] = As[row * AS_PITCH + col + 4];
            a[mt][3] = As[(row + 8) * AS_PITCH + col + 4];
        }
        uint32_t b[4][2];
        #pragma unroll
        for (int nt = 0; nt < 4; nt++) {
            int kk = kb + (lane & 3);
            int nn = wn * 32 + nt * 8 + (lane >> 2);
            b[nt][0] = Bs[kk * BS_PITCH + nn];
            b[nt][1] = Bs[(kk + 4) * BS_PITCH + nn];
        }
        #pragma unroll
        for (int mt = 0; mt < 2; mt++)
            #pragma unroll
            for (int nt = 0; nt < 4; nt++)
                mma_tf32(acc[mt][nt], a[mt], b[nt]);
    }
}

// load A tile (raw tf32 bits) via cp.async: row pitch ldA floats
__device__ __forceinline__ void load_a_tile(
    uint32_t* As, const float* A, long ldA, int row0, int k0, int M, int tid) {
    int r = tid >> 1, kc = (tid & 1) * 16;
    int gr = row0 + r;
    const float* src = A + (long)gr * ldA + k0 + kc;
    uint32_t dst = smem_u32(As + r * AS_PITCH + kc);
    int ok = (gr < M) ? 16 : 0;
    #pragma unroll
    for (int i = 0; i < 4; i++) cp16(dst + i * 16, src + i * 4, ok);
}

// load B tile (pre-converted tf32 bits) via cp.async
__device__ __forceinline__ void load_b_tile(
    uint32_t* Bs, const uint32_t* B, int ldB, int k0, int col0, int tid) {
    int k = tid >> 3, n0 = (tid & 7) * 8;
    const uint32_t* src = B + (long)(k0 + k) * ldB + col0 + n0;
    uint32_t dst = smem_u32(Bs + k * BS_PITCH + n0);
    cp16(dst, src, 16);
    cp16(dst + 16, src + 4, 16);
}

// kernel 4: per-head layer-1 GEMM, epilogue = +b1, ELU, f2tf -> agg1 bits
__global__ __launch_bounds__(256) void tf32_gemm_h(
    const float* __restrict__ A, const uint32_t* __restrict__ Btf,
    const float* __restrict__ b1, float* __restrict__ C, int M) {
    extern __shared__ uint32_t dyn[];
    uint32_t* As0 = dyn;
    uint32_t* Bs0 = dyn + 2 * AS_SZ;
    int tid = threadIdx.x, lane = tid & 31, wid = tid >> 5;
    int wm = wid >> 1, wn = wid & 1;
    int row0 = blockIdx.y * 128;
    int h = blockIdx.z;
    const float* Ah = A + h * FIN;
    float acc[2][4][4] = {};

    load_a_tile(As0, Ah, DAGG, row0, 0, M, tid);
    load_b_tile(Bs0, Btf, D1, 0, h * 64, tid);
    CP_COMMIT();
    #pragma unroll
    for (int kt = 0; kt < 4; kt++) {
        int st = kt & 1;
        if (kt + 1 < 4) {
            int st2 = (kt + 1) & 1;
            load_a_tile(As0 + st2 * AS_SZ, Ah, DAGG, row0, (kt + 1) * 32, M, tid);
            load_b_tile(Bs0 + st2 * BS_SZ, Btf, D1, (kt + 1) * 32, h * 64, tid);
            CP_COMMIT();
            CP_WAIT(1);
        } else {
            CP_WAIT(0);
        }
        __syncthreads();
        mma_block(As0 + st * AS_SZ, Bs0 + st * BS_SZ, lane, wm, wn, acc);
        __syncthreads();
    }
    // epilogue: bias + ELU + tf32 bits
    uint32_t* Ch = (uint32_t*)(C) + h * 64;
    #pragma unroll
    for (int mt = 0; mt < 2; mt++) {
        #pragma unroll
        for (int nt = 0; nt < 4; nt++) {
            int r0 = row0 + wm * 32 + mt * 16 + (lane >> 2);
            int c0 = wn * 32 + nt * 8 + (lane & 3) * 2;
            float bb0 = __ldg(b1 + h * 64 + c0);
            float bb1 = __ldg(b1 + h * 64 + c0 + 1);
            float v0 = acc[mt][nt][0] + bb0, v1 = acc[mt][nt][1] + bb1;
            float v2 = acc[mt][nt][2] + bb0, v3 = acc[mt][nt][3] + bb1;
            v0 = v0 > 0.f ? v0 : (__expf(v0) - 1.f);
            v1 = v1 > 0.f ? v1 : (__expf(v1) - 1.f);
            v2 = v2 > 0.f ? v2 : (__expf(v2) - 1.f);
            v3 = v3 > 0.f ? v3 : (__expf(v3) - 1.f);
            if (r0 < M)
                *(uint2*)(Ch + (long)r0 * D1 + c0) = make_uint2(f2tf(v0), f2tf(v1));
            if (r0 + 8 < M)
                *(uint2*)(Ch + (long)(r0 + 8) * D1 + c0) = make_uint2(f2tf(v2), f2tf(v3));
        }
    }
}

// kernel 5: layer-2 GEMM (A = agg1 tf32 bits) + fused alpha2 epilogue
__global__ __launch_bounds__(256) void tf32_gemm2_alpha(
    const float* __restrict__ A, const uint32_t* __restrict__ Btf,
    const float* __restrict__ att_s, const float* __restrict__ att_d,
    float* __restrict__ C, float* __restrict__ as2, float* __restrict__ ad2,
    int M) {
    extern __shared__ uint32_t dyn[];
    uint32_t* As0 = dyn;
    uint32_t* Bs0 = dyn + 2 * AS_SZ;
    __shared__ float att_sh[2][64];
    __shared__ float ps_sh[128], pd_sh[128];
    int tid = threadIdx.x, lane = tid & 31, wid = tid >> 5;
    int wm = wid >> 1, wn = wid & 1;
    int row0 = blockIdx.y * 128;
    if (tid < 64)       att_sh[0][tid] = att_s[tid];
    else if (tid < 128) att_sh[1][tid - 64] = att_d[tid - 64];
    float acc[2][4][4] = {};

    load_a_tile(As0, A, D1, row0, 0, M, tid);
    load_b_tile(Bs0, Btf, D2, 0, 0, tid);
    CP_COMMIT();
    #pragma unroll
    for (int kt = 0; kt < 8; kt++) {
        int st = kt & 1;
        if (kt + 1 < 8) {
            int st2 = (kt + 1) & 1;
            load_a_tile(As0 + st2 * AS_SZ, A, D1, row0, (kt + 1) * 32, M, tid);
            load_b_tile(Bs0 + st2 * BS_SZ, Btf, D2, (kt + 1) * 32, 0, tid);
            CP_COMMIT();
            CP_WAIT(1);
        } else {
            CP_WAIT(0);
        }
        __syncthreads();
        mma_block(As0 + st * AS_SZ, Bs0 + st * BS_SZ, lane, wm, wn, acc);
        __syncthreads();
    }
    // store xl2
    #pragma unroll
    for (int mt = 0; mt < 2; mt++) {
        #pragma unroll
        for (int nt = 0; nt < 4; nt++) {
            int r0 = row0 + wm * 32 + mt * 16 + (lane >> 2);
            int c0 = wn * 32 + nt * 8 + (lane & 3) * 2;
            if (r0 < M)
                *(float2*)(C + (long)r0 * D2 + c0) =
                    make_float2(acc[mt][nt][0], acc[mt][nt][1]);
            if (r0 + 8 < M)
                *(float2*)(C + (long)(r0 + 8) * D2 + c0) =
                    make_float2(acc[mt][nt][2], acc[mt][nt][3]);
        }
    }
    // fused alpha2
    float ps[4] = {}, pd[4] = {};
    #pragma unroll
    for (int mt = 0; mt < 2; mt++) {
        #pragma unroll
        for (int half = 0; half < 2; half++) {
            int ri = mt * 2 + half;
            #pragma unroll
            for (int nt = 0; nt < 4; nt++) {
                #pragma unroll
                for (int i = 0; i < 2; i++) {
                    int col = wn * 32 + nt * 8 + (lane & 3) * 2 + i;
                    float v = acc[mt][nt][half * 2 + i];
                    ps[ri] += v * att_sh[0][col];
                    pd[ri] += v * att_sh[1][col];
                }
            }
        }
    }
    #pragma unroll
    for (int ri = 0; ri < 4; ri++) {
        ps[ri] += __shfl_xor_sync(0xFFFFFFFFu, ps[ri], 1);
        ps[ri] += __shfl_xor_sync(0xFFFFFFFFu, ps[ri], 2);
        pd[ri] += __shfl_xor_sync(0xFFFFFFFFu, pd[ri], 1);
        pd[ri] += __shfl_xor_sync(0xFFFFFFFFu, pd[ri], 2);
    }
    __syncthreads();
    if (wn == 0 && (lane & 3) == 0) {
        #pragma unroll
        for (int mt = 0; mt < 2; mt++)
            #pragma unroll
            for (int half = 0; half < 2; half++) {
                int r = wm * 32 + mt * 16 + half * 8 + (lane >> 2);
                ps_sh[r] = ps[mt * 2 + half];
                pd_sh[r] = pd[mt * 2 + half];
            }
    }
    __syncthreads();
    if (wn == 1 && (lane & 3) == 0) {
        #pragma unroll
        for (int mt = 0; mt < 2; mt++)
            #pragma unroll
            for (int half = 0; half < 2; half++) {
                int r = wm * 32 + mt * 16 + half * 8 + (lane >> 2);
                ps_sh[r] += ps[mt * 2 + half];
                pd_sh[r] += pd[mt * 2 + half];
            }
    }
    __syncthreads();
    if (tid < 128) {
        int gr = row0 + tid;
        if (gr < M) { as2[gr] = ps_sh[tid]; ad2[gr] = pd_sh[tid]; }
    }
}

// ================= kernel 6: gather layer2 (f32x2) ===========================
__global__ __launch_bounds__(256) void gather2_kernel(
    const int* __restrict__ cnt, const int* __restrict__ srcs,
    const float* __restrict__ asrc, const float* __restrict__ adst,
    const float* __restrict__ xl, const float* __restrict__ b2,
    float* __restrict__ out) {
    __shared__ int sm_s[8][32];
    __shared__ ull sm_e[8][32];
    int wslot = threadIdx.x >> 5;
    int node = blockIdx.x * 8 + wslot;
    if (node >= NNODES) return;
    int lane = threadIdx.x & 31;
    int deg = min(cnt[node], CAP);
    const int* bucket = srcs + node * CAP;
    float adv = adst[node];
    ull acc = 0ull;
    float exs = 0.f;
    for (int base = 0; base < deg; base += 32) {
        int j = base + lane;
        if (j < deg) {
            int sv = __ldg(bucket + j);
            float v = __ldg(asrc + sv) + adv;
            v = v > 0.f ? v : v * NEG_SLOPE;
            float ex = __expf(v);
            exs += ex;
            sm_s[wslot][lane] = sv;
            sm_e[wslot][lane] = pack2(ex, ex);
        }
        __syncwarp();
        int m = min(32, deg - base);
        for (int t = 0; t < m; t++) {
            int s  = sm_s[wslot][t];
            ull ed = sm_e[wslot][t];
            ull v  = *(const ull*)(xl + (long)s * D2 + lane * 2);
            acc = ffma2(v, ed, acc);
        }
        __syncwarp();
    }
    #pragma unroll
    for (int off = 16; off; off >>= 1)
        exs += __shfl_xor_sync(0xFFFFFFFFu, exs, off);
    float inv = 1.f / exs;
    float a0, a1;
    unpack2(acc, a0, a1);
    float2 bb = *(const float2*)(b2 + lane * 2);
    *(float2*)(out + (long)node * D2 + lane * 2) =
        make_float2(a0 * inv + bb.x, a1 * inv + bb.y);
}

// ================= launch ====================================================
extern "C" void kernel_launch(void* const* d_in, const int* in_sizes, int n_in,
                              void* d_out, int out_size) {
    const float* x     = (const float*)d_in[0];
    const int*   ei    = (const int*)d_in[1];
    const float* W1    = (const float*)d_in[2];
    const float* at_s1 = (const float*)d_in[3];
    const float* at_d1 = (const float*)d_in[4];
    const float* b1    = (const float*)d_in[5];
    const float* W2    = (const float*)d_in[6];
    const float* at_s2 = (const float*)d_in[7];
    const float* at_d2 = (const float*)d_in[8];
    const float* b2    = (const float*)d_in[9];
    float* out = (float*)d_out;

    float *aggx, *agg1, *xl2, *ws1, *wd1, *as1, *ad1, *as2, *ad2;
    uint32_t *w1tf, *w2tf;
    int *cnt, *srcs;
    cudaGetSymbolAddress((void**)&aggx, g_aggx);
    cudaGetSymbolAddress((void**)&agg1, g_agg1);
    cudaGetSymbolAddress((void**)&xl2,  g_xl2);
    cudaGetSymbolAddress((void**)&w1tf, g_w1tf);
    cudaGetSymbolAddress((void**)&w2tf, g_w2tf);
    cudaGetSymbolAddress((void**)&ws1,  g_ws1);
    cudaGetSymbolAddress((void**)&wd1,  g_wd1);
    cudaGetSymbolAddress((void**)&as1,  g_as1);
    cudaGetSymbolAddress((void**)&ad1,  g_ad1);
    cudaGetSymbolAddress((void**)&as2,  g_as2);
    cudaGetSymbolAddress((void**)&ad2,  g_ad2);
    cudaGetSymbolAddress((void**)&cnt,  g_cnt);
    cudaGetSymbolAddress((void**)&srcs, g_srcs);

    cudaFuncSetAttribute(tf32_gemm_h,
                         cudaFuncAttributeMaxDynamicSharedMemorySize, GEMM_DYN);
    cudaFuncSetAttribute(tf32_gemm2_alpha,
                         cudaFuncAttributeMaxDynamicSharedMemorySize, GEMM_DYN);

    // 1: zero cnt + w1prep + W1/W2 tf32 conversion
    init_prep_kernel<<<195, 512>>>(cnt, W1, W2, at_s1, at_d1, ws1, wd1, w1tf, w2tf);
    // 2: bucket scatter + alpha1
    scatter_alpha1_kernel<<<SCAT_BLK + ALPHA1_BLK, 256>>>(
        ei, cnt, srcs, x, ws1, wd1, as1, ad1);
    // 3: gather layer 1 (tf32-bit output)
    gather1_kernel<<<(NNODES + 7) / 8, 256>>>(cnt, srcs, as1, ad1, x, aggx);
    // 4: per-head GEMM1 (+bias+ELU epilogue, tf32-bit agg1)
    tf32_gemm_h<<<dim3(1, (NNODES + 127) / 128, H1), 256, GEMM_DYN>>>(
        aggx, w1tf, b1, agg1, NNODES);
    // 5: GEMM2 + fused alpha2
    tf32_gemm2_alpha<<<dim3(1, (NNODES + 127) / 128), 256, GEMM_DYN>>>(
        agg1, w2tf, at_s2, at_d2, xl2, as2, ad2, NNODES);
    // 6: gather layer 2 -> d_out
    gather2_kernel<<<(NNODES + 7) / 8, 256>>>(cnt, srcs, as2, ad2, xl2, b2, out);
}

// round 14
// speedup vs baseline: 1.1456x; 1.1456x over previous
#include <cuda_runtime.h>
#include <cuda_fp16.h>
#include <cstdint>

#define NNODES 50000
#define NEDGES 800000
#define ETOT   850000
#define FIN    128
#define H1     4
#define D1     256   // H1*C1
#define D2     64
#define DAGG   512   // H1*FIN (halfs per node)
#define CAP    64
#define NEG_SLOPE 0.2f
#define SCAT_BLK  3321      // ceil(850000/256)
#define ALPHA1_BLK 6250     // ceil(50000/8)

typedef unsigned long long ull;

// ---------------- scratch (static device globals) ---------------------------
static __device__ __half g_aggx[NNODES * DAGG];   // fp16, 51.2 MB
static __device__ __half g_agg1[NNODES * D1];     // fp16 (post bias+ELU), 25.6 MB
static __device__ float  g_xl2 [NNODES * D2];
static __device__ __half g_w1t [D1 * FIN];        // W1^T fp16, n-major
static __device__ __half g_w2t [D2 * D1];         // W2^T fp16, n-major
static __device__ float  g_ws1 [FIN * H1];
static __device__ float  g_wd1 [FIN * H1];
static __device__ float  g_as1 [NNODES * H1];
static __device__ float  g_ad1 [NNODES * H1];
static __device__ float  g_as2 [NNODES];
static __device__ float  g_ad2 [NNODES];
static __device__ int    g_cnt [NNODES];
static __device__ int    g_srcs[NNODES * CAP];

__device__ __forceinline__ void edge_nodes(const int* __restrict__ ei,
                                           int e, int& s, int& d) {
    if (e < NEDGES) { s = ei[e]; d = ei[NEDGES + e]; }
    else            { s = e - NEDGES; d = s; }
}

__device__ __forceinline__ void mma_f16(float c[4], const uint32_t a[4],
                                        const uint32_t b[2]) {
    asm volatile(
        "mma.sync.aligned.m16n8k16.row.col.f32.f16.f16.f32 "
        "{%0,%1,%2,%3}, {%4,%5,%6,%7}, {%8,%9}, {%0,%1,%2,%3};"
        : "+f"(c[0]), "+f"(c[1]), "+f"(c[2]), "+f"(c[3])
        : "r"(a[0]), "r"(a[1]), "r"(a[2]), "r"(a[3]), "r"(b[0]), "r"(b[1]));
}

__device__ __forceinline__ ull pack2(float lo, float hi) {
    ull r;
    asm("mov.b64 %0, {%1, %2};" : "=l"(r) : "f"(lo), "f"(hi));
    return r;
}
__device__ __forceinline__ void unpack2(ull v, float& lo, float& hi) {
    asm("mov.b64 {%0, %1}, %2;" : "=f"(lo), "=f"(hi) : "l"(v));
}
__device__ __forceinline__ ull ffma2(ull a, ull b, ull c) {
    ull d;
    asm("fma.rn.f32x2 %0, %1, %2, %3;" : "=l"(d) : "l"(a), "l"(b), "l"(c));
    return d;
}

// ================= kernel 1: zero cnt + w1prep + W1/W2 -> fp16 transposed ====
// blocks 0..97: zero cnt | 98: ws/wd | 99..162: W1^T | 163..194: W2^T
__global__ __launch_bounds__(512) void init_prep_kernel(
    int* __restrict__ cnt, const float* __restrict__ W1,
    const float* __restrict__ W2,
    const float* __restrict__ a_s, const float* __restrict__ a_d,
    float* __restrict__ ws, float* __restrict__ wd,
    __half* __restrict__ w1t, __half* __restrict__ w2t) {
    int b = blockIdx.x;
    if (b < 98) {
        int i = b * 512 + threadIdx.x;
        if (i < NNODES) cnt[i] = 0;
    } else if (b == 98) {
        int t = threadIdx.x;
        int c = t >> 2, h = t & 3;
        float accs = 0.f, accd = 0.f;
        #pragma unroll 8
        for (int j = 0; j < 64; j++) {
            float w = W1[c * D1 + h * 64 + j];
            accs += w * a_s[h * 64 + j];
            accd += w * a_d[h * 64 + j];
        }
        ws[c * 4 + h] = accs;
        wd[c * 4 + h] = accd;
    } else if (b < 163) {
        int i = (b - 99) * 512 + threadIdx.x;       // over D1*FIN = 32768
        int n = i / FIN, k = i % FIN;
        w1t[i] = __float2half_rn(W1[k * D1 + n]);
    } else {
        int i = (b - 163) * 512 + threadIdx.x;      // over D2*D1 = 16384
        int n = i / D1, k = i % D1;
        w2t[i] = __float2half_rn(W2[k * D2 + n]);
    }
}

// ================= kernel 2: bucket scatter + alpha1 (merged) ================
__global__ __launch_bounds__(256) void scatter_alpha1_kernel(
    const int* __restrict__ ei, int* __restrict__ cnt, int* __restrict__ srcs,
    const float* __restrict__ x, const float* __restrict__ ws,
    const float* __restrict__ wd,
    float* __restrict__ asrc, float* __restrict__ adst) {
    if (blockIdx.x < SCAT_BLK) {
        int e = blockIdx.x * 256 + threadIdx.x;
        if (e >= ETOT) return;
        int s, d; edge_nodes(ei, e, s, d);
        int slot = atomicAdd(&cnt[d], 1);
        if (slot < CAP) srcs[d * CAP + slot] = s;
    } else {
        int w = (blockIdx.x - SCAT_BLK) * 8 + (threadIdx.x >> 5);
        int lane = threadIdx.x & 31;
        if (w >= NNODES) return;
        const float* row = x + (long)w * FIN;
        float ps[4] = {}, pd[4] = {};
        #pragma unroll
        for (int j = 0; j < 4; j++) {
            int c = lane + j * 32;
            float v = row[c];
            float4 a = *(const float4*)(ws + c * 4);
            float4 b = *(const float4*)(wd + c * 4);
            ps[0] += v * a.x; ps[1] += v * a.y; ps[2] += v * a.z; ps[3] += v * a.w;
            pd[0] += v * b.x; pd[1] += v * b.y; pd[2] += v * b.z; pd[3] += v * b.w;
        }
        #pragma unroll
        for (int off = 16; off; off >>= 1) {
            #pragma unroll
            for (int h = 0; h < 4; h++) {
                ps[h] += __shfl_xor_sync(0xFFFFFFFFu, ps[h], off);
                pd[h] += __shfl_xor_sync(0xFFFFFFFFu, pd[h], off);
            }
        }
        if (lane == 0) {
            *(float4*)(asrc + w * 4) = make_float4(ps[0], ps[1], ps[2], ps[3]);
            *(float4*)(adst + w * 4) = make_float4(pd[0], pd[1], pd[2], pd[3]);
        }
    }
}

// ================= kernel 3: gather layer1 (writes fp16 aggx) ================
__global__ __launch_bounds__(256) void gather1_kernel(
    const int* __restrict__ cnt, const int* __restrict__ srcs,
    const float* __restrict__ asrc, const float* __restrict__ adst,
    const float* __restrict__ x, __half* __restrict__ aggx) {
    __shared__ int sm_s  [8][32];
    __shared__ ull sm_dup[8][32][4];
    int wslot = threadIdx.x >> 5;
    int node = blockIdx.x * 8 + wslot;
    if (node >= NNODES) return;
    int lane = threadIdx.x & 31;
    int deg = min(cnt[node], CAP);
    const int* bucket = srcs + node * CAP;
    float4 ad = *(const float4*)(adst + node * 4);
    ull accl[4], acch[4];
    #pragma unroll
    for (int h = 0; h < 4; h++) { accl[h] = 0ull; acch[h] = 0ull; }
    float exs[4] = {};
    for (int base = 0; base < deg; base += 32) {
        int j = base + lane;
        if (j < deg) {
            int sv = __ldg(bucket + j);
            float4 as = *(const float4*)(asrc + sv * 4);
            float v;
            float4 ex;
            v = as.x + ad.x; v = v > 0.f ? v : v * NEG_SLOPE; ex.x = __expf(v);
            v = as.y + ad.y; v = v > 0.f ? v : v * NEG_SLOPE; ex.y = __expf(v);
            v = as.z + ad.z; v = v > 0.f ? v : v * NEG_SLOPE; ex.z = __expf(v);
            v = as.w + ad.w; v = v > 0.f ? v : v * NEG_SLOPE; ex.w = __expf(v);
            exs[0] += ex.x; exs[1] += ex.y; exs[2] += ex.z; exs[3] += ex.w;
            sm_s[wslot][lane] = sv;
            sm_dup[wslot][lane][0] = pack2(ex.x, ex.x);
            sm_dup[wslot][lane][1] = pack2(ex.y, ex.y);
            sm_dup[wslot][lane][2] = pack2(ex.z, ex.z);
            sm_dup[wslot][lane][3] = pack2(ex.w, ex.w);
        }
        __syncwarp();
        int m = min(32, deg - base);
        for (int t = 0; t < m; t++) {
            int s = sm_s[wslot][t];
            ulonglong2 e01 = *(const ulonglong2*)&sm_dup[wslot][t][0];
            ulonglong2 e23 = *(const ulonglong2*)&sm_dup[wslot][t][2];
            ulonglong2 v = __ldg((const ulonglong2*)(x + (long)s * FIN + lane * 4));
            accl[0] = ffma2(v.x, e01.x, accl[0]);
            acch[0] = ffma2(v.y, e01.x, acch[0]);
            accl[1] = ffma2(v.x, e01.y, accl[1]);
            acch[1] = ffma2(v.y, e01.y, acch[1]);
            accl[2] = ffma2(v.x, e23.x, accl[2]);
            acch[2] = ffma2(v.y, e23.x, acch[2]);
            accl[3] = ffma2(v.x, e23.y, accl[3]);
            acch[3] = ffma2(v.y, e23.y, acch[3]);
        }
        __syncwarp();
    }
    #pragma unroll
    for (int off = 16; off; off >>= 1)
        #pragma unroll
        for (int h = 0; h < 4; h++)
            exs[h] += __shfl_xor_sync(0xFFFFFFFFu, exs[h], off);
    __half* o = aggx + (long)node * DAGG + lane * 4;
    #pragma unroll
    for (int h = 0; h < 4; h++) {
        float inv = 1.f / exs[h];
        float a0, a1, a2, a3;
        unpack2(accl[h], a0, a1);
        unpack2(acch[h], a2, a3);
        __half2 p0 = __floats2half2_rn(a0 * inv, a1 * inv);
        __half2 p1 = __floats2half2_rn(a2 * inv, a3 * inv);
        uint2 u;
        u.x = *(uint32_t*)&p0;
        u.y = *(uint32_t*)&p1;
        *(uint2*)(o + h * FIN) = u;
    }
}

// ================= fp16 GEMM core (BM=128, BN=64, 8 warps) ===================
#define PA 136                     // halfs per As row (128 + 8 pad)
#define PB 136
#define GEMM_DYN ((128 * PA + 64 * PB) * 2)

__device__ __forceinline__ void mma_chunk_f16(
    const __half* __restrict__ As, const __half* __restrict__ Bs,
    int lane, int wm, int wn, float acc[2][4][4]) {
    #pragma unroll
    for (int ks = 0; ks < 8; ks++) {
        int k0 = ks * 16;
        uint32_t a[2][4];
        #pragma unroll
        for (int mt = 0; mt < 2; mt++) {
            const __half* pr = As + (wm * 32 + mt * 16 + (lane >> 2)) * PA
                               + k0 + (lane & 3) * 2;
            a[mt][0] = *(const uint32_t*)pr;
            a[mt][1] = *(const uint32_t*)(pr + 8 * PA);
            a[mt][2] = *(const uint32_t*)(pr + 8);
            a[mt][3] = *(const uint32_t*)(pr + 8 * PA + 8);
        }
        uint32_t b[4][2];
        #pragma unroll
        for (int nt = 0; nt < 4; nt++) {
            const __half* pb = Bs + (wn * 32 + nt * 8 + (lane >> 2)) * PB
                               + k0 + (lane & 3) * 2;
            b[nt][0] = *(const uint32_t*)pb;
            b[nt][1] = *(const uint32_t*)(pb + 8);
        }
        #pragma unroll
        for (int mt = 0; mt < 2; mt++)
            #pragma unroll
            for (int nt = 0; nt < 4; nt++)
                mma_f16(acc[mt][nt], a[mt], b[nt]);
    }
}

// load a 128x128-half A chunk: thread -> half row (64 halfs = 8 uint4)
__device__ __forceinline__ void load_a128(
    __half* As, const __half* A, long ldA, int row0, int k0, int M, int tid) {
    int r = tid >> 1, c0 = (tid & 1) * 64;
    int gr = row0 + r;
    uint4* dst = (uint4*)(As + r * PA + c0);
    if (gr < M) {
        const uint4* src = (const uint4*)(A + (long)gr * ldA + k0 + c0);
        #pragma unroll
        for (int i = 0; i < 8; i++) dst[i] = src[i];
    } else {
        uint4 z = make_uint4(0, 0, 0, 0);
        #pragma unroll
        for (int i = 0; i < 8; i++) dst[i] = z;
    }
}

// load a 64x128-half B chunk (n-major): thread -> quarter row (32 halfs)
__device__ __forceinline__ void load_b128(
    __half* Bs, const __half* Bt, long ldB, int n0, int k0, int tid) {
    int r = tid >> 2, c0 = (tid & 3) * 32;
    const uint4* src = (const uint4*)(Bt + (long)(n0 + r) * ldB + k0 + c0);
    uint4* dst = (uint4*)(Bs + r * PB + c0);
    #pragma unroll
    for (int i = 0; i < 4; i++) dst[i] = src[i];
}

// kernel 4: per-head layer-1 GEMM (fp16), epilogue = +b1, ELU -> fp16 agg1
__global__ __launch_bounds__(256) void f16_gemm_h(
    const __half* __restrict__ A, const __half* __restrict__ Bt,
    const float* __restrict__ b1, __half* __restrict__ C, int M) {
    extern __shared__ __half sm[];
    __half* As = sm;
    __half* Bs = sm + 128 * PA;
    int tid = threadIdx.x, lane = tid & 31, wid = tid >> 5;
    int wm = wid >> 1, wn = wid & 1;
    int row0 = blockIdx.y * 128;
    int h = blockIdx.z;
    load_a128(As, A, DAGG, row0, h * FIN, M, tid);
    load_b128(Bs, Bt, FIN, h * 64, 0, tid);
    __syncthreads();
    float acc[2][4][4] = {};
    mma_chunk_f16(As, Bs, lane, wm, wn, acc);
    // epilogue: bias + ELU -> fp16
    __half* Ch = C + h * 64;
    #pragma unroll
    for (int mt = 0; mt < 2; mt++) {
        #pragma unroll
        for (int nt = 0; nt < 4; nt++) {
            int r0 = row0 + wm * 32 + mt * 16 + (lane >> 2);
            int c0 = wn * 32 + nt * 8 + (lane & 3) * 2;
            float bb0 = __ldg(b1 + h * 64 + c0);
            float bb1 = __ldg(b1 + h * 64 + c0 + 1);
            float v0 = acc[mt][nt][0] + bb0, v1 = acc[mt][nt][1] + bb1;
            float v2 = acc[mt][nt][2] + bb0, v3 = acc[mt][nt][3] + bb1;
            v0 = v0 > 0.f ? v0 : (__expf(v0) - 1.f);
            v1 = v1 > 0.f ? v1 : (__expf(v1) - 1.f);
            v2 = v2 > 0.f ? v2 : (__expf(v2) - 1.f);
            v3 = v3 > 0.f ? v3 : (__expf(v3) - 1.f);
            __half2 p01 = __floats2half2_rn(v0, v1);
            __half2 p23 = __floats2half2_rn(v2, v3);
            if (r0 < M)
                *(uint32_t*)(Ch + (long)r0 * D1 + c0) = *(uint32_t*)&p01;
            if (r0 + 8 < M)
                *(uint32_t*)(Ch + (long)(r0 + 8) * D1 + c0) = *(uint32_t*)&p23;
        }
    }
}

// kernel 5: layer-2 GEMM (fp16, K=256 in 2 chunks) + fused alpha2 epilogue
__global__ __launch_bounds__(256) void f16_gemm2_alpha(
    const __half* __restrict__ A, const __half* __restrict__ Bt,
    const float* __restrict__ att_s, const float* __restrict__ att_d,
    float* __restrict__ C, float* __restrict__ as2, float* __restrict__ ad2,
    int M) {
    extern __shared__ __half sm[];
    __half* As = sm;
    __half* Bs = sm + 128 * PA;
    __shared__ float att_sh[2][64];
    __shared__ float ps_sh[128], pd_sh[128];
    int tid = threadIdx.x, lane = tid & 31, wid = tid >> 5;
    int wm = wid >> 1, wn = wid & 1;
    int row0 = blockIdx.y * 128;
    if (tid < 64)       att_sh[0][tid] = att_s[tid];
    else if (tid < 128) att_sh[1][tid - 64] = att_d[tid - 64];
    float acc[2][4][4] = {};
    #pragma unroll
    for (int kt = 0; kt < 2; kt++) {
        if (kt) __syncthreads();
        load_a128(As, A, D1, row0, kt * 128, M, tid);
        load_b128(Bs, Bt, D1, 0, kt * 128, tid);
        __syncthreads();
        mma_chunk_f16(As, Bs, lane, wm, wn, acc);
    }
    // store xl2 (fp32)
    #pragma unroll
    for (int mt = 0; mt < 2; mt++) {
        #pragma unroll
        for (int nt = 0; nt < 4; nt++) {
            int r0 = row0 + wm * 32 + mt * 16 + (lane >> 2);
            int c0 = wn * 32 + nt * 8 + (lane & 3) * 2;
            if (r0 < M)
                *(float2*)(C + (long)r0 * D2 + c0) =
                    make_float2(acc[mt][nt][0], acc[mt][nt][1]);
            if (r0 + 8 < M)
                *(float2*)(C + (long)(r0 + 8) * D2 + c0) =
                    make_float2(acc[mt][nt][2], acc[mt][nt][3]);
        }
    }
    // fused alpha2
    float ps[4] = {}, pd[4] = {};
    #pragma unroll
    for (int mt = 0; mt < 2; mt++) {
        #pragma unroll
        for (int half = 0; half < 2; half++) {
            int ri = mt * 2 + half;
            #pragma unroll
            for (int nt = 0; nt < 4; nt++) {
                #pragma unroll
                for (int i = 0; i < 2; i++) {
                    int col = wn * 32 + nt * 8 + (lane & 3) * 2 + i;
                    float v = acc[mt][nt][half * 2 + i];
                    ps[ri] += v * att_sh[0][col];
                    pd[ri] += v * att_sh[1][col];
                }
            }
        }
    }
    #pragma unroll
    for (int ri = 0; ri < 4; ri++) {
        ps[ri] += __shfl_xor_sync(0xFFFFFFFFu, ps[ri], 1);
        ps[ri] += __shfl_xor_sync(0xFFFFFFFFu, ps[ri], 2);
        pd[ri] += __shfl_xor_sync(0xFFFFFFFFu, pd[ri], 1);
        pd[ri] += __shfl_xor_sync(0xFFFFFFFFu, pd[ri], 2);
    }
    __syncthreads();
    if (wn == 0 && (lane & 3) == 0) {
        #pragma unroll
        for (int mt = 0; mt < 2; mt++)
            #pragma unroll
            for (int half = 0; half < 2; half++) {
                int r = wm * 32 + mt * 16 + half * 8 + (lane >> 2);
                ps_sh[r] = ps[mt * 2 + half];
                pd_sh[r] = pd[mt * 2 + half];
            }
    }
    __syncthreads();
    if (wn == 1 && (lane & 3) == 0) {
        #pragma unroll
        for (int mt = 0; mt < 2; mt++)
            #pragma unroll
            for (int half = 0; half < 2; half++) {
                int r = wm * 32 + mt * 16 + half * 8 + (lane >> 2);
                ps_sh[r] += ps[mt * 2 + half];
                pd_sh[r] += pd[mt * 2 + half];
            }
    }
    __syncthreads();
    if (tid < 128) {
        int gr = row0 + tid;
        if (gr < M) { as2[gr] = ps_sh[tid]; ad2[gr] = pd_sh[tid]; }
    }
}

// ================= kernel 6: gather layer2 (f32x2) ===========================
__global__ __launch_bounds__(256) void gather2_kernel(
    const int* __restrict__ cnt, const int* __restrict__ srcs,
    const float* __restrict__ asrc, const float* __restrict__ adst,
    const float* __restrict__ xl, const float* __restrict__ b2,
    float* __restrict__ out) {
    __shared__ int sm_s[8][32];
    __shared__ ull sm_e[8][32];
    int wslot = threadIdx.x >> 5;
    int node = blockIdx.x * 8 + wslot;
    if (node >= NNODES) return;
    int lane = threadIdx.x & 31;
    int deg = min(cnt[node], CAP);
    const int* bucket = srcs + node * CAP;
    float adv = adst[node];
    ull acc = 0ull;
    float exs = 0.f;
    for (int base = 0; base < deg; base += 32) {
        int j = base + lane;
        if (j < deg) {
            int sv = __ldg(bucket + j);
            float v = __ldg(asrc + sv) + adv;
            v = v > 0.f ? v : v * NEG_SLOPE;
            float ex = __expf(v);
            exs += ex;
            sm_s[wslot][lane] = sv;
            sm_e[wslot][lane] = pack2(ex, ex);
        }
        __syncwarp();
        int m = min(32, deg - base);
        for (int t = 0; t < m; t++) {
            int s  = sm_s[wslot][t];
            ull ed = sm_e[wslot][t];
            ull v  = *(const ull*)(xl + (long)s * D2 + lane * 2);
            acc = ffma2(v, ed, acc);
        }
        __syncwarp();
    }
    #pragma unroll
    for (int off = 16; off; off >>= 1)
        exs += __shfl_xor_sync(0xFFFFFFFFu, exs, off);
    float inv = 1.f / exs;
    float a0, a1;
    unpack2(acc, a0, a1);
    float2 bb = *(const float2*)(b2 + lane * 2);
    *(float2*)(out + (long)node * D2 + lane * 2) =
        make_float2(a0 * inv + bb.x, a1 * inv + bb.y);
}

// ================= launch ====================================================
extern "C" void kernel_launch(void* const* d_in, const int* in_sizes, int n_in,
                              void* d_out, int out_size) {
    const float* x     = (const float*)d_in[0];
    const int*   ei    = (const int*)d_in[1];
    const float* W1    = (const float*)d_in[2];
    const float* at_s1 = (const float*)d_in[3];
    const float* at_d1 = (const float*)d_in[4];
    const float* b1    = (const float*)d_in[5];
    const float* W2    = (const float*)d_in[6];
    const float* at_s2 = (const float*)d_in[7];
    const float* at_d2 = (const float*)d_in[8];
    const float* b2    = (const float*)d_in[9];
    float* out = (float*)d_out;

    __half *aggx, *agg1, *w1t, *w2t;
    float *xl2, *ws1, *wd1, *as1, *ad1, *as2, *ad2;
    int *cnt, *srcs;
    cudaGetSymbolAddress((void**)&aggx, g_aggx);
    cudaGetSymbolAddress((void**)&agg1, g_agg1);
    cudaGetSymbolAddress((void**)&xl2,  g_xl2);
    cudaGetSymbolAddress((void**)&w1t,  g_w1t);
    cudaGetSymbolAddress((void**)&w2t,  g_w2t);
    cudaGetSymbolAddress((void**)&ws1,  g_ws1);
    cudaGetSymbolAddress((void**)&wd1,  g_wd1);
    cudaGetSymbolAddress((void**)&as1,  g_as1);
    cudaGetSymbolAddress((void**)&ad1,  g_ad1);
    cudaGetSymbolAddress((void**)&as2,  g_as2);
    cudaGetSymbolAddress((void**)&ad2,  g_ad2);
    cudaGetSymbolAddress((void**)&cnt,  g_cnt);
    cudaGetSymbolAddress((void**)&srcs, g_srcs);

    cudaFuncSetAttribute(f16_gemm_h,
                         cudaFuncAttributeMaxDynamicSharedMemorySize, GEMM_DYN);
    cudaFuncSetAttribute(f16_gemm2_alpha,
                         cudaFuncAttributeMaxDynamicSharedMemorySize, GEMM_DYN);

    // 1: zero cnt + w1prep + fp16 transposed weights
    init_prep_kernel<<<195, 512>>>(cnt, W1, W2, at_s1, at_d1, ws1, wd1, w1t, w2t);
    // 2: bucket scatter + alpha1
    scatter_alpha1_kernel<<<SCAT_BLK + ALPHA1_BLK, 256>>>(
        ei, cnt, srcs, x, ws1, wd1, as1, ad1);
    // 3: gather layer 1 (fp16 aggx)
    gather1_kernel<<<(NNODES + 7) / 8, 256>>>(cnt, srcs, as1, ad1, x, aggx);
    // 4: per-head GEMM1 (fp16) + bias/ELU epilogue
    f16_gemm_h<<<dim3(1, (NNODES + 127) / 128, H1), 256, GEMM_DYN>>>(
        aggx, w1t, b1, agg1, NNODES);
    // 5: GEMM2 (fp16) + fused alpha2
    f16_gemm2_alpha<<<dim3(1, (NNODES + 127) / 128), 256, GEMM_DYN>>>(
        agg1, w2t, at_s2, at_d2, xl2, as2, ad2, NNODES);
    // 6: gather layer 2 -> d_out
    gather2_kernel<<<(NNODES + 7) / 8, 256>>>(cnt, srcs, as2, ad2, xl2, b2, out);
}

// round 15
// speedup vs baseline: 1.1539x; 1.0072x over previous
#include <cuda_runtime.h>
#include <cuda_fp16.h>
#include <cstdint>

#define NNODES 50000
#define NEDGES 800000
#define ETOT   850000
#define FIN    128
#define H1     4
#define D1     256   // H1*C1
#define D2     64
#define DAGG   512   // H1*FIN (halfs per node)
#define CAP    64
#define NEG_SLOPE 0.2f
#define SCAT_BLK  3321      // ceil(850000/256)
#define ALPHA1_BLK 6250     // ceil(50000/8)

typedef unsigned long long ull;

// ---------------- scratch (static device globals) ---------------------------
static __device__ __half g_aggx[NNODES * DAGG];   // fp16, 51.2 MB
static __device__ __half g_agg1[NNODES * D1];     // fp16 (post bias+ELU), 25.6 MB
static __device__ float  g_xl2 [NNODES * D2];
static __device__ __half g_w1t [D1 * FIN];        // W1^T fp16, n-major
static __device__ __half g_w2t [D2 * D1];         // W2^T fp16, n-major
static __device__ float  g_ws1 [FIN * H1];
static __device__ float  g_wd1 [FIN * H1];
static __device__ float  g_as1 [NNODES * H1];
static __device__ float  g_ad1 [NNODES * H1];
static __device__ float  g_as2 [NNODES];
static __device__ float  g_ad2 [NNODES];
static __device__ int    g_cnt [NNODES];
static __device__ int    g_srcs[NNODES * CAP];

__device__ __forceinline__ void edge_nodes(const int* __restrict__ ei,
                                           int e, int& s, int& d) {
    if (e < NEDGES) { s = ei[e]; d = ei[NEDGES + e]; }
    else            { s = e - NEDGES; d = s; }
}

__device__ __forceinline__ void mma_f16(float c[4], const uint32_t a[4],
                                        const uint32_t b[2]) {
    asm volatile(
        "mma.sync.aligned.m16n8k16.row.col.f32.f16.f16.f32 "
        "{%0,%1,%2,%3}, {%4,%5,%6,%7}, {%8,%9}, {%0,%1,%2,%3};"
        : "+f"(c[0]), "+f"(c[1]), "+f"(c[2]), "+f"(c[3])
        : "r"(a[0]), "r"(a[1]), "r"(a[2]), "r"(a[3]), "r"(b[0]), "r"(b[1]));
}

__device__ __forceinline__ ull pack2(float lo, float hi) {
    ull r;
    asm("mov.b64 %0, {%1, %2};" : "=l"(r) : "f"(lo), "f"(hi));
    return r;
}
__device__ __forceinline__ void unpack2(ull v, float& lo, float& hi) {
    asm("mov.b64 {%0, %1}, %2;" : "=f"(lo), "=f"(hi) : "l"(v));
}
__device__ __forceinline__ ull ffma2(ull a, ull b, ull c) {
    ull d;
    asm("fma.rn.f32x2 %0, %1, %2, %3;" : "=l"(d) : "l"(a), "l"(b), "l"(c));
    return d;
}

__device__ __forceinline__ uint32_t smem_u32(const void* p) {
    return (uint32_t)__cvta_generic_to_shared(p);
}
__device__ __forceinline__ void ldsm_x4(uint32_t& r0, uint32_t& r1,
                                        uint32_t& r2, uint32_t& r3,
                                        uint32_t addr) {
    asm volatile("ldmatrix.sync.aligned.m8n8.x4.shared.b16 {%0,%1,%2,%3}, [%4];"
                 : "=r"(r0), "=r"(r1), "=r"(r2), "=r"(r3) : "r"(addr));
}

// ================= kernel 1: zero cnt + w1prep + W1/W2 -> fp16 transposed ====
__global__ __launch_bounds__(512) void init_prep_kernel(
    int* __restrict__ cnt, const float* __restrict__ W1,
    const float* __restrict__ W2,
    const float* __restrict__ a_s, const float* __restrict__ a_d,
    float* __restrict__ ws, float* __restrict__ wd,
    __half* __restrict__ w1t, __half* __restrict__ w2t) {
    int b = blockIdx.x;
    if (b < 98) {
        int i = b * 512 + threadIdx.x;
        if (i < NNODES) cnt[i] = 0;
    } else if (b == 98) {
        int t = threadIdx.x;
        int c = t >> 2, h = t & 3;
        float accs = 0.f, accd = 0.f;
        #pragma unroll 8
        for (int j = 0; j < 64; j++) {
            float w = W1[c * D1 + h * 64 + j];
            accs += w * a_s[h * 64 + j];
            accd += w * a_d[h * 64 + j];
        }
        ws[c * 4 + h] = accs;
        wd[c * 4 + h] = accd;
    } else if (b < 163) {
        int i = (b - 99) * 512 + threadIdx.x;       // over D1*FIN = 32768
        int n = i / FIN, k = i % FIN;
        w1t[i] = __float2half_rn(W1[k * D1 + n]);
    } else {
        int i = (b - 163) * 512 + threadIdx.x;      // over D2*D1 = 16384
        int n = i / D1, k = i % D1;
        w2t[i] = __float2half_rn(W2[k * D2 + n]);
    }
}

// ================= kernel 2: bucket scatter + alpha1 (merged) ================
__global__ __launch_bounds__(256) void scatter_alpha1_kernel(
    const int* __restrict__ ei, int* __restrict__ cnt, int* __restrict__ srcs,
    const float* __restrict__ x, const float* __restrict__ ws,
    const float* __restrict__ wd,
    float* __restrict__ asrc, float* __restrict__ adst) {
    if (blockIdx.x < SCAT_BLK) {
        int e = blockIdx.x * 256 + threadIdx.x;
        if (e >= ETOT) return;
        int s, d; edge_nodes(ei, e, s, d);
        int slot = atomicAdd(&cnt[d], 1);
        if (slot < CAP) srcs[d * CAP + slot] = s;
    } else {
        int w = (blockIdx.x - SCAT_BLK) * 8 + (threadIdx.x >> 5);
        int lane = threadIdx.x & 31;
        if (w >= NNODES) return;
        const float* row = x + (long)w * FIN;
        float ps[4] = {}, pd[4] = {};
        #pragma unroll
        for (int j = 0; j < 4; j++) {
            int c = lane + j * 32;
            float v = row[c];
            float4 a = *(const float4*)(ws + c * 4);
            float4 b = *(const float4*)(wd + c * 4);
            ps[0] += v * a.x; ps[1] += v * a.y; ps[2] += v * a.z; ps[3] += v * a.w;
            pd[0] += v * b.x; pd[1] += v * b.y; pd[2] += v * b.z; pd[3] += v * b.w;
        }
        #pragma unroll
        for (int off = 16; off; off >>= 1) {
            #pragma unroll
            for (int h = 0; h < 4; h++) {
                ps[h] += __shfl_xor_sync(0xFFFFFFFFu, ps[h], off);
                pd[h] += __shfl_xor_sync(0xFFFFFFFFu, pd[h], off);
            }
        }
        if (lane == 0) {
            *(float4*)(asrc + w * 4) = make_float4(ps[0], ps[1], ps[2], ps[3]);
            *(float4*)(adst + w * 4) = make_float4(pd[0], pd[1], pd[2], pd[3]);
        }
    }
}

// ================= kernel 3: gather layer1 (writes fp16 aggx) ================
__global__ __launch_bounds__(256) void gather1_kernel(
    const int* __restrict__ cnt, const int* __restrict__ srcs,
    const float* __restrict__ asrc, const float* __restrict__ adst,
    const float* __restrict__ x, __half* __restrict__ aggx) {
    __shared__ int sm_s  [8][32];
    __shared__ ull sm_dup[8][32][4];
    int wslot = threadIdx.x >> 5;
    int node = blockIdx.x * 8 + wslot;
    if (node >= NNODES) return;
    int lane = threadIdx.x & 31;
    int deg = min(cnt[node], CAP);
    const int* bucket = srcs + node * CAP;
    float4 ad = *(const float4*)(adst + node * 4);
    ull accl[4], acch[4];
    #pragma unroll
    for (int h = 0; h < 4; h++) { accl[h] = 0ull; acch[h] = 0ull; }
    float exs[4] = {};
    for (int base = 0; base < deg; base += 32) {
        int j = base + lane;
        if (j < deg) {
            int sv = __ldg(bucket + j);
            float4 as = *(const float4*)(asrc + sv * 4);
            float v;
            float4 ex;
            v = as.x + ad.x; v = v > 0.f ? v : v * NEG_SLOPE; ex.x = __expf(v);
            v = as.y + ad.y; v = v > 0.f ? v : v * NEG_SLOPE; ex.y = __expf(v);
            v = as.z + ad.z; v = v > 0.f ? v : v * NEG_SLOPE; ex.z = __expf(v);
            v = as.w + ad.w; v = v > 0.f ? v : v * NEG_SLOPE; ex.w = __expf(v);
            exs[0] += ex.x; exs[1] += ex.y; exs[2] += ex.z; exs[3] += ex.w;
            sm_s[wslot][lane] = sv;
            sm_dup[wslot][lane][0] = pack2(ex.x, ex.x);
            sm_dup[wslot][lane][1] = pack2(ex.y, ex.y);
            sm_dup[wslot][lane][2] = pack2(ex.z, ex.z);
            sm_dup[wslot][lane][3] = pack2(ex.w, ex.w);
        }
        __syncwarp();
        int m = min(32, deg - base);
        for (int t = 0; t < m; t++) {
            int s = sm_s[wslot][t];
            ulonglong2 e01 = *(const ulonglong2*)&sm_dup[wslot][t][0];
            ulonglong2 e23 = *(const ulonglong2*)&sm_dup[wslot][t][2];
            ulonglong2 v = __ldg((const ulonglong2*)(x + (long)s * FIN + lane * 4));
            accl[0] = ffma2(v.x, e01.x, accl[0]);
            acch[0] = ffma2(v.y, e01.x, acch[0]);
            accl[1] = ffma2(v.x, e01.y, accl[1]);
            acch[1] = ffma2(v.y, e01.y, acch[1]);
            accl[2] = ffma2(v.x, e23.x, accl[2]);
            acch[2] = ffma2(v.y, e23.x, acch[2]);
            accl[3] = ffma2(v.x, e23.y, accl[3]);
            acch[3] = ffma2(v.y, e23.y, acch[3]);
        }
        __syncwarp();
    }
    #pragma unroll
    for (int off = 16; off; off >>= 1)
        #pragma unroll
        for (int h = 0; h < 4; h++)
            exs[h] += __shfl_xor_sync(0xFFFFFFFFu, exs[h], off);
    __half* o = aggx + (long)node * DAGG + lane * 4;
    #pragma unroll
    for (int h = 0; h < 4; h++) {
        float inv = 1.f / exs[h];
        float a0, a1, a2, a3;
        unpack2(accl[h], a0, a1);
        unpack2(acch[h], a2, a3);
        __half2 p0 = __floats2half2_rn(a0 * inv, a1 * inv);
        __half2 p1 = __floats2half2_rn(a2 * inv, a3 * inv);
        uint2 u;
        u.x = *(uint32_t*)&p0;
        u.y = *(uint32_t*)&p1;
        *(uint2*)(o + h * FIN) = u;
    }
}

// ================= fp16 GEMM core (BM=128, BN=64, 8 warps, ldmatrix) =========
#define PA 136                     // halfs per As row (128 + 8 pad); 272 B pitch
#define PB 136
#define GEMM_DYN ((128 * PA + 64 * PB) * 2)

__device__ __forceinline__ void mma_chunk_f16(
    const __half* __restrict__ As, const __half* __restrict__ Bs,
    int lane, int wm, int wn, float acc[2][4][4]) {
    // per-thread ldmatrix base addresses (k0 = 0)
    uint32_t abase[2], bbase[2];
    #pragma unroll
    for (int mt = 0; mt < 2; mt++)
        abase[mt] = smem_u32(As + (wm * 32 + mt * 16 + ((lane >> 3) & 1) * 8
                                   + (lane & 7)) * PA + (lane >> 4) * 8);
    #pragma unroll
    for (int p = 0; p < 2; p++)
        bbase[p] = smem_u32(Bs + (wn * 32 + (2 * p + (lane >> 4)) * 8
                                  + (lane & 7)) * PB + ((lane >> 3) & 1) * 8);
    #pragma unroll
    for (int ks = 0; ks < 8; ks++) {
        uint32_t koff = ks * 32;   // 16 halfs = 32 bytes
        uint32_t a[2][4], b[4][2];
        ldsm_x4(a[0][0], a[0][1], a[0][2], a[0][3], abase[0] + koff);
        ldsm_x4(a[1][0], a[1][1], a[1][2], a[1][3], abase[1] + koff);
        ldsm_x4(b[0][0], b[0][1], b[1][0], b[1][1], bbase[0] + koff);
        ldsm_x4(b[2][0], b[2][1], b[3][0], b[3][1], bbase[1] + koff);
        #pragma unroll
        for (int mt = 0; mt < 2; mt++)
            #pragma unroll
            for (int nt = 0; nt < 4; nt++)
                mma_f16(acc[mt][nt], a[mt], b[nt]);
    }
}

// load a 128x128-half A chunk: thread -> half row (64 halfs = 8 uint4)
__device__ __forceinline__ void load_a128(
    __half* As, const __half* A, long ldA, int row0, int k0, int M, int tid) {
    int r = tid >> 1, c0 = (tid & 1) * 64;
    int gr = row0 + r;
    uint4* dst = (uint4*)(As + r * PA + c0);
    if (gr < M) {
        const uint4* src = (const uint4*)(A + (long)gr * ldA + k0 + c0);
        #pragma unroll
        for (int i = 0; i < 8; i++) dst[i] = src[i];
    } else {
        uint4 z = make_uint4(0, 0, 0, 0);
        #pragma unroll
        for (int i = 0; i < 8; i++) dst[i] = z;
    }
}

// load a 64x128-half B chunk (n-major): thread -> quarter row (32 halfs)
__device__ __forceinline__ void load_b128(
    __half* Bs, const __half* Bt, long ldB, int n0, int k0, int tid) {
    int r = tid >> 2, c0 = (tid & 3) * 32;
    const uint4* src = (const uint4*)(Bt + (long)(n0 + r) * ldB + k0 + c0);
    uint4* dst = (uint4*)(Bs + r * PB + c0);
    #pragma unroll
    for (int i = 0; i < 4; i++) dst[i] = src[i];
}

// kernel 4: per-head layer-1 GEMM (fp16), epilogue = +b1, ELU -> fp16 agg1
__global__ __launch_bounds__(256) void f16_gemm_h(
    const __half* __restrict__ A, const __half* __restrict__ Bt,
    const float* __restrict__ b1, __half* __restrict__ C, int M) {
    extern __shared__ __half sm[];
    __half* As = sm;
    __half* Bs = sm + 128 * PA;
    int tid = threadIdx.x, lane = tid & 31, wid = tid >> 5;
    int wm = wid >> 1, wn = wid & 1;
    int row0 = blockIdx.y * 128;
    int h = blockIdx.z;
    load_a128(As, A, DAGG, row0, h * FIN, M, tid);
    load_b128(Bs, Bt, FIN, h * 64, 0, tid);
    __syncthreads();
    float acc[2][4][4] = {};
    mma_chunk_f16(As, Bs, lane, wm, wn, acc);
    // epilogue: bias + ELU -> fp16
    __half* Ch = C + h * 64;
    #pragma unroll
    for (int mt = 0; mt < 2; mt++) {
        #pragma unroll
        for (int nt = 0; nt < 4; nt++) {
            int r0 = row0 + wm * 32 + mt * 16 + (lane >> 2);
            int c0 = wn * 32 + nt * 8 + (lane & 3) * 2;
            float bb0 = __ldg(b1 + h * 64 + c0);
            float bb1 = __ldg(b1 + h * 64 + c0 + 1);
            float v0 = acc[mt][nt][0] + bb0, v1 = acc[mt][nt][1] + bb1;
            float v2 = acc[mt][nt][2] + bb0, v3 = acc[mt][nt][3] + bb1;
            v0 = v0 > 0.f ? v0 : (__expf(v0) - 1.f);
            v1 = v1 > 0.f ? v1 : (__expf(v1) - 1.f);
            v2 = v2 > 0.f ? v2 : (__expf(v2) - 1.f);
            v3 = v3 > 0.f ? v3 : (__expf(v3) - 1.f);
            __half2 p01 = __floats2half2_rn(v0, v1);
            __half2 p23 = __floats2half2_rn(v2, v3);
            if (r0 < M)
                *(uint32_t*)(Ch + (long)r0 * D1 + c0) = *(uint32_t*)&p01;
            if (r0 + 8 < M)
                *(uint32_t*)(Ch + (long)(r0 + 8) * D1 + c0) = *(uint32_t*)&p23;
        }
    }
}

// kernel 5: layer-2 GEMM (fp16, K=256 in 2 chunks) + fused alpha2 epilogue
__global__ __launch_bounds__(256) void f16_gemm2_alpha(
    const __half* __restrict__ A, const __half* __restrict__ Bt,
    const float* __restrict__ att_s, const float* __restrict__ att_d,
    float* __restrict__ C, float* __restrict__ as2, float* __restrict__ ad2,
    int M) {
    extern __shared__ __half sm[];
    __half* As = sm;
    __half* Bs = sm + 128 * PA;
    __shared__ float att_sh[2][64];
    __shared__ float ps_sh[128], pd_sh[128];
    int tid = threadIdx.x, lane = tid & 31, wid = tid >> 5;
    int wm = wid >> 1, wn = wid & 1;
    int row0 = blockIdx.y * 128;
    if (tid < 64)       att_sh[0][tid] = att_s[tid];
    else if (tid < 128) att_sh[1][tid - 64] = att_d[tid - 64];
    float acc[2][4][4] = {};
    #pragma unroll
    for (int kt = 0; kt < 2; kt++) {
        if (kt) __syncthreads();
        load_a128(As, A, D1, row0, kt * 128, M, tid);
        load_b128(Bs, Bt, D1, 0, kt * 128, tid);
        __syncthreads();
        mma_chunk_f16(As, Bs, lane, wm, wn, acc);
    }
    // store xl2 (fp32)
    #pragma unroll
    for (int mt = 0; mt < 2; mt++) {
        #pragma unroll
        for (int nt = 0; nt < 4; nt++) {
            int r0 = row0 + wm * 32 + mt * 16 + (lane >> 2);
            int c0 = wn * 32 + nt * 8 + (lane & 3) * 2;
            if (r0 < M)
                *(float2*)(C + (long)r0 * D2 + c0) =
                    make_float2(acc[mt][nt][0], acc[mt][nt][1]);
            if (r0 + 8 < M)
                *(float2*)(C + (long)(r0 + 8) * D2 + c0) =
                    make_float2(acc[mt][nt][2], acc[mt][nt][3]);
        }
    }
    // fused alpha2
    float ps[4] = {}, pd[4] = {};
    #pragma unroll
    for (int mt = 0; mt < 2; mt++) {
        #pragma unroll
        for (int half = 0; half < 2; half++) {
            int ri = mt * 2 + half;
            #pragma unroll
            for (int nt = 0; nt < 4; nt++) {
                #pragma unroll
                for (int i = 0; i < 2; i++) {
                    int col = wn * 32 + nt * 8 + (lane & 3) * 2 + i;
                    float v = acc[mt][nt][half * 2 + i];
                    ps[ri] += v * att_sh[0][col];
                    pd[ri] += v * att_sh[1][col];
                }
            }
        }
    }
    #pragma unroll
    for (int ri = 0; ri < 4; ri++) {
        ps[ri] += __shfl_xor_sync(0xFFFFFFFFu, ps[ri], 1);
        ps[ri] += __shfl_xor_sync(0xFFFFFFFFu, ps[ri], 2);
        pd[ri] += __shfl_xor_sync(0xFFFFFFFFu, pd[ri], 1);
        pd[ri] += __shfl_xor_sync(0xFFFFFFFFu, pd[ri], 2);
    }
    __syncthreads();
    if (wn == 0 && (lane & 3) == 0) {
        #pragma unroll
        for (int mt = 0; mt < 2; mt++)
            #pragma unroll
            for (int half = 0; half < 2; half++) {
                int r = wm * 32 + mt * 16 + half * 8 + (lane >> 2);
                ps_sh[r] = ps[mt * 2 + half];
                pd_sh[r] = pd[mt * 2 + half];
            }
    }
    __syncthreads();
    if (wn == 1 && (lane & 3) == 0) {
        #pragma unroll
        for (int mt = 0; mt < 2; mt++)
            #pragma unroll
            for (int half = 0; half < 2; half++) {
                int r = wm * 32 + mt * 16 + half * 8 + (lane >> 2);
                ps_sh[r] += ps[mt * 2 + half];
                pd_sh[r] += pd[mt * 2 + half];
            }
    }
    __syncthreads();
    if (tid < 128) {
        int gr = row0 + tid;
        if (gr < M) { as2[gr] = ps_sh[tid]; ad2[gr] = pd_sh[tid]; }
    }
}

// ================= kernel 6: gather layer2 (f32x2) ===========================
__global__ __launch_bounds__(256) void gather2_kernel(
    const int* __restrict__ cnt, const int* __restrict__ srcs,
    const float* __restrict__ asrc, const float* __restrict__ adst,
    const float* __restrict__ xl, const float* __restrict__ b2,
    float* __restrict__ out) {
    __shared__ int sm_s[8][32];
    __shared__ ull sm_e[8][32];
    int wslot = threadIdx.x >> 5;
    int node = blockIdx.x * 8 + wslot;
    if (node >= NNODES) return;
    int lane = threadIdx.x & 31;
    int deg = min(cnt[node], CAP);
    const int* bucket = srcs + node * CAP;
    float adv = adst[node];
    ull acc = 0ull;
    float exs = 0.f;
    for (int base = 0; base < deg; base += 32) {
        int j = base + lane;
        if (j < deg) {
            int sv = __ldg(bucket + j);
            float v = __ldg(asrc + sv) + adv;
            v = v > 0.f ? v : v * NEG_SLOPE;
            float ex = __expf(v);
            exs += ex;
            sm_s[wslot][lane] = sv;
            sm_e[wslot][lane] = pack2(ex, ex);
        }
        __syncwarp();
        int m = min(32, deg - base);
        for (int t = 0; t < m; t++) {
            int s  = sm_s[wslot][t];
            ull ed = sm_e[wslot][t];
            ull v  = *(const ull*)(xl + (long)s * D2 + lane * 2);
            acc = ffma2(v, ed, acc);
        }
        __syncwarp();
    }
    #pragma unroll
    for (int off = 16; off; off >>= 1)
        exs += __shfl_xor_sync(0xFFFFFFFFu, exs, off);
    float inv = 1.f / exs;
    float a0, a1;
    unpack2(acc, a0, a1);
    float2 bb = *(const float2*)(b2 + lane * 2);
    *(float2*)(out + (long)node * D2 + lane * 2) =
        make_float2(a0 * inv + bb.x, a1 * inv + bb.y);
}

// ================= launch ====================================================
extern "C" void kernel_launch(void* const* d_in, const int* in_sizes, int n_in,
                              void* d_out, int out_size) {
    const float* x     = (const float*)d_in[0];
    const int*   ei    = (const int*)d_in[1];
    const float* W1    = (const float*)d_in[2];
    const float* at_s1 = (const float*)d_in[3];
    const float* at_d1 = (const float*)d_in[4];
    const float* b1    = (const float*)d_in[5];
    const float* W2    = (const float*)d_in[6];
    const float* at_s2 = (const float*)d_in[7];
    const float* at_d2 = (const float*)d_in[8];
    const float* b2    = (const float*)d_in[9];
    float* out = (float*)d_out;

    __half *aggx, *agg1, *w1t, *w2t;
    float *xl2, *ws1, *wd1, *as1, *ad1, *as2, *ad2;
    int *cnt, *srcs;
    cudaGetSymbolAddress((void**)&aggx, g_aggx);
    cudaGetSymbolAddress((void**)&agg1, g_agg1);
    cudaGetSymbolAddress((void**)&xl2,  g_xl2);
    cudaGetSymbolAddress((void**)&w1t,  g_w1t);
    cudaGetSymbolAddress((void**)&w2t,  g_w2t);
    cudaGetSymbolAddress((void**)&ws1,  g_ws1);
    cudaGetSymbolAddress((void**)&wd1,  g_wd1);
    cudaGetSymbolAddress((void**)&as1,  g_as1);
    cudaGetSymbolAddress((void**)&ad1,  g_ad1);
    cudaGetSymbolAddress((void**)&as2,  g_as2);
    cudaGetSymbolAddress((void**)&ad2,  g_ad2);
    cudaGetSymbolAddress((void**)&cnt,  g_cnt);
    cudaGetSymbolAddress((void**)&srcs, g_srcs);

    cudaFuncSetAttribute(f16_gemm_h,
                         cudaFuncAttributeMaxDynamicSharedMemorySize, GEMM_DYN);
    cudaFuncSetAttribute(f16_gemm2_alpha,
                         cudaFuncAttributeMaxDynamicSharedMemorySize, GEMM_DYN);

    // 1: zero cnt + w1prep + fp16 transposed weights
    init_prep_kernel<<<195, 512>>>(cnt, W1, W2, at_s1, at_d1, ws1, wd1, w1t, w2t);
    // 2: bucket scatter + alpha1
    scatter_alpha1_kernel<<<SCAT_BLK + ALPHA1_BLK, 256>>>(
        ei, cnt, srcs, x, ws1, wd1, as1, ad1);
    // 3: gather layer 1 (fp16 aggx)
    gather1_kernel<<<(NNODES + 7) / 8, 256>>>(cnt, srcs, as1, ad1, x, aggx);
    // 4: per-head GEMM1 (fp16) + bias/ELU epilogue
    f16_gemm_h<<<dim3(1, (NNODES + 127) / 128, H1), 256, GEMM_DYN>>>(
        aggx, w1t, b1, agg1, NNODES);
    // 5: GEMM2 (fp16) + fused alpha2
    f16_gemm2_alpha<<<dim3(1, (NNODES + 127) / 128), 256, GEMM_DYN>>>(
        agg1, w2t, at_s2, at_d2, xl2, as2, ad2, NNODES);
    // 6: gather layer 2 -> d_out
    gather2_kernel<<<(NNODES + 7) / 8, 256>>>(cnt, srcs, as2, ad2, xl2, b2, out);
}